// round 12
// baseline (speedup 1.0000x reference)
#include <cuda_runtime.h>
#include <cuda_fp16.h>
#include <cstdint>

#define T_  4096
#define B_  4
#define D_  1024
#define H_  8
#define R_  (T_*B_)   // 16384 rows

// ---------------- scratch -------------------------------------------------
__device__ __align__(16) __half g_xn [(size_t)R_*D_];
__device__ __align__(16) __half g_xtn[(size_t)R_*D_];
__device__ __align__(16) __half g_q  [(size_t)R_*D_];
__device__ __align__(16) __half g_k  [(size_t)R_*D_];   // holds exp(k + bias)
__device__ __align__(16) __half g_v  [(size_t)R_*D_];
__device__ __align__(16) __half g_wh[3u*1024*1024];
__device__ __align__(16) float g_csum[B_*D_];
__device__ __align__(16) float g_attp[4ull*32*16384];    // [split][bh][l][d] fp32
__device__ __align__(16) __half g_att [(size_t)32*16384]; // [bh][l][d] fp16

// ---------------- helpers -------------------------------------------------
__device__ __forceinline__ void cp_async16(void* smem, const void* gmem) {
    unsigned sa = (unsigned)__cvta_generic_to_shared(smem);
    asm volatile("cp.async.cg.shared.global [%0], [%1], 16;\n" :: "r"(sa), "l"(gmem));
}
#define CP_COMMIT()  asm volatile("cp.async.commit_group;\n")
#define CP_WAIT(n)   asm volatile("cp.async.wait_group %0;\n" :: "n"(n))

__device__ __forceinline__ void mma16(float* d, const uint32_t* a, const uint32_t* b) {
    asm volatile(
        "mma.sync.aligned.m16n8k16.row.col.f32.f16.f16.f32 "
        "{%0,%1,%2,%3}, {%4,%5,%6,%7}, {%8,%9}, {%0,%1,%2,%3};"
        : "+f"(d[0]), "+f"(d[1]), "+f"(d[2]), "+f"(d[3])
        : "r"(a[0]), "r"(a[1]), "r"(a[2]), "r"(a[3]), "r"(b[0]), "r"(b[1]));
}
__device__ __forceinline__ void ldsm4(uint32_t* r, uint32_t addr) {
    asm volatile("ldmatrix.sync.aligned.m8n8.x4.shared.b16 {%0,%1,%2,%3}, [%4];"
        : "=r"(r[0]), "=r"(r[1]), "=r"(r[2]), "=r"(r[3]) : "r"(addr));
}
__device__ __forceinline__ void ldsm4t(uint32_t* r, uint32_t addr) {
    asm volatile("ldmatrix.sync.aligned.m8n8.x4.trans.shared.b16 {%0,%1,%2,%3}, [%4];"
        : "=r"(r[0]), "=r"(r[1]), "=r"(r[2]), "=r"(r[3]) : "r"(addr));
}

// ---------------- weight convert to fp16 (+ csum zeroing) ------------------
__global__ void cvt_w1(const float* __restrict__ w, int which) {
    int off = blockIdx.x*256 + threadIdx.x;       // 262144 float4s
    if (which == 0 && blockIdx.x < 16)
        g_csum[blockIdx.x*256 + threadIdx.x] = 0.f;
    float4 v = *(const float4*)(w + (size_t)off*4);
    __half2 h0 = __floats2half2_rn(v.x, v.y);
    __half2 h1 = __floats2half2_rn(v.z, v.w);
    *(uint2*)(g_wh + (size_t)which*1048576 + (size_t)off*4) =
        make_uint2(*(unsigned*)&h0, *(unsigned*)&h1);
}

// ---------------- LayerNorm (both branches, fp16 out, float4 loads) --------
__global__ void ln_kernel(const float* __restrict__ x,
                          const float* __restrict__ nw, const float* __restrict__ nb,
                          const float* __restrict__ tw, const float* __restrict__ tb) {
    int rin = blockIdx.x;
    int t = rin / B_, b = rin % B_;
    const float* xr = x + (size_t)rin * D_;
    int tid = threadIdx.x;

    float4 v = *(const float4*)(xr + tid*4);
    float s  = v.x + v.y + v.z + v.w;
    float s2 = v.x*v.x + v.y*v.y + v.z*v.z + v.w*v.w;

    __shared__ float red[40];
#pragma unroll
    for (int o = 16; o; o >>= 1) {
        s  += __shfl_xor_sync(0xffffffffu, s,  o);
        s2 += __shfl_xor_sync(0xffffffffu, s2, o);
    }
    if ((tid & 31) == 0) { red[tid>>5] = s; red[8 + (tid>>5)] = s2; }
    __syncthreads();
    if (tid < 32) {
        float a = (tid < 8) ? red[tid]     : 0.f;
        float c = (tid < 8) ? red[8 + tid] : 0.f;
#pragma unroll
        for (int o = 4; o; o >>= 1) {
            a += __shfl_xor_sync(0xffffffffu, a, o);
            c += __shfl_xor_sync(0xffffffffu, c, o);
        }
        if (tid == 0) { red[32] = a; red[33] = c; }
    }
    __syncthreads();
    float mean = red[32] * (1.f / D_);
    float var  = red[33] * (1.f / D_) - mean*mean;
    float rstd = rsqrtf(var + 1e-5f);

    float4 w1 = *(const float4*)(nw + tid*4);
    float4 b1 = *(const float4*)(nb + tid*4);
    float4 w2 = *(const float4*)(tw + tid*4);
    float4 b2 = *(const float4*)(tb + tid*4);

    float z0 = (v.x - mean)*rstd, z1 = (v.y - mean)*rstd;
    float z2 = (v.z - mean)*rstd, z3 = (v.w - mean)*rstd;

    size_t ro = ((size_t)b*T_ + t) * D_ + tid*4;
    __half2 n0 = __floats2half2_rn(z0*w1.x + b1.x, z1*w1.y + b1.y);
    __half2 n1 = __floats2half2_rn(z2*w1.z + b1.z, z3*w1.w + b1.w);
    *(uint2*)(g_xn + ro) = make_uint2(*(unsigned*)&n0, *(unsigned*)&n1);
    __half2 t0 = __floats2half2_rn(z0*w2.x + b2.x, z1*w2.y + b2.y);
    __half2 t1 = __floats2half2_rn(z2*w2.z + b2.z, z3*w2.w + b2.w);
    *(uint2*)(g_xtn + ro) = make_uint2(*(unsigned*)&t0, *(unsigned*)&t1);
}

// ---------------- fp16 GEMM: 128x128 block, 8 warps, 32x64 warp tile -------
// mode 1 (k): stores exp(acc + bias) AND accumulates column sums into g_csum.
__global__ void __launch_bounds__(256, 2)
gemm_f16(const float* __restrict__ bq, const float* __restrict__ bk,
         const float* __restrict__ bv) {
    extern __shared__ char smraw[];
    uint32_t sbase = (uint32_t)__cvta_generic_to_shared(smraw);
    int mode = blockIdx.z;
    const __half* A = (mode == 0) ? g_xn : g_xtn;
    const __half* W = g_wh + (size_t)mode*1048576;
    __half*       C = (mode == 0) ? g_q : (mode == 1 ? g_k : g_v);
    const float*  bias = (mode == 0) ? bq : (mode == 1 ? bk : bv);

    int tid = threadIdx.x;
    int lane = tid & 31, wid = tid >> 5;
    int wm = wid & 3, wn = wid >> 2;      // 4x2 warps, warp tile 32x64
    int bm = blockIdx.y * 128, bn = blockIdx.x * 128;

    int q = lane >> 3, r = lane & 7;
    int grp = lane >> 2, tg = lane & 3;

    float acc[2][8][4];
#pragma unroll
    for (int i = 0; i < 2; i++)
#pragma unroll
        for (int j = 0; j < 8; j++)
#pragma unroll
            for (int e = 0; e < 4; e++) acc[i][j][e] = 0.f;

#define LOAD_CHUNK(S, KC)                                                        \
    {                                                                            \
        char* As_ = smraw + (S)*32768;                                           \
        char* Bs_ = As_ + 16384;                                                 \
        _Pragma("unroll")                                                        \
        for (int i = 0; i < 4; i++) {                                            \
            int idx = tid + i*256;                                               \
            int rr = idx >> 3, g = idx & 7;                                      \
            cp_async16(As_ + rr*128 + ((g ^ (rr & 7)) << 4),                     \
                       A + (size_t)(bm + rr)*1024 + (KC)*64 + g*8);              \
            cp_async16(Bs_ + rr*128 + ((g ^ (rr & 7)) << 4),                     \
                       W + (size_t)(bn + rr)*1024 + (KC)*64 + g*8);              \
        }                                                                        \
        CP_COMMIT();                                                             \
    }

    LOAD_CHUNK(0, 0)
    LOAD_CHUNK(1, 1)

    for (int c = 0; c < 16; c++) {
        if (c < 15) { CP_WAIT(1); } else { CP_WAIT(0); }
        __syncthreads();
        if (c + 2 < 16) { LOAD_CHUNK((c + 2) % 3, c + 2) }

        uint32_t Asm = sbase + (c % 3)*32768;
        uint32_t Bsm = Asm + 16384;
#pragma unroll
        for (int ks = 0; ks < 4; ks++) {
            uint32_t a[2][4], bfr[4][4];
#pragma unroll
            for (int mi = 0; mi < 2; mi++) {
                int row = wm*32 + mi*16 + r + ((q & 1) << 3);
                int kh  = ks*16 + ((q >> 1) << 3);
                ldsm4(a[mi], Asm + row*128 + (((kh >> 3) ^ (row & 7)) << 4));
            }
#pragma unroll
            for (int nj = 0; nj < 4; nj++) {
                int nrow = wn*64 + nj*16 + r + ((q >> 1) << 3);
                int kh   = ks*16 + ((q & 1) << 3);
                ldsm4(bfr[nj], Bsm + nrow*128 + (((kh >> 3) ^ (nrow & 7)) << 4));
            }
#pragma unroll
            for (int mi = 0; mi < 2; mi++)
#pragma unroll
                for (int nj = 0; nj < 4; nj++) {
                    mma16(acc[mi][nj*2 + 0], a[mi], &bfr[nj][0]);
                    mma16(acc[mi][nj*2 + 1], a[mi], &bfr[nj][2]);
                }
        }
    }
#undef LOAD_CHUNK

    float cs0[8], cs1[8];
#pragma unroll
    for (int ni = 0; ni < 8; ni++) { cs0[ni] = 0.f; cs1[ni] = 0.f; }

#pragma unroll
    for (int mi = 0; mi < 2; mi++)
#pragma unroll
        for (int ni = 0; ni < 8; ni++) {
            int row = bm + wm*32 + mi*16 + grp;
            int col = bn + wn*64 + ni*8 + tg*2;
            float b0 = bias[col], b1 = bias[col + 1];
            float v0 = acc[mi][ni][0] + b0, v1 = acc[mi][ni][1] + b1;
            float v2 = acc[mi][ni][2] + b0, v3 = acc[mi][ni][3] + b1;
            if (mode == 1) {
                v0 = __expf(v0); v1 = __expf(v1);
                v2 = __expf(v2); v3 = __expf(v3);
                cs0[ni] += v0 + v2;
                cs1[ni] += v1 + v3;
            }
            *(__half2*)(C + (size_t)row*1024 + col) = __floats2half2_rn(v0, v1);
            *(__half2*)(C + (size_t)(row + 8)*1024 + col) = __floats2half2_rn(v2, v3);
        }

    if (mode == 1) {
#pragma unroll
        for (int ni = 0; ni < 8; ni++) {
#pragma unroll
            for (int o = 4; o <= 16; o <<= 1) {
                cs0[ni] += __shfl_xor_sync(0xffffffffu, cs0[ni], o);
                cs1[ni] += __shfl_xor_sync(0xffffffffu, cs1[ni], o);
            }
        }
        __syncthreads();
        float* buf = (float*)smraw;      // [8 warps][64 cols]
        if (lane < 4) {
#pragma unroll
            for (int ni = 0; ni < 8; ni++) {
                buf[wid*64 + ni*8 + tg*2    ] = cs0[ni];
                buf[wid*64 + ni*8 + tg*2 + 1] = cs1[ni];
            }
        }
        __syncthreads();
        if (tid < 128) {
            int wnn = tid >> 6, cl = tid & 63;
            float s = buf[(wnn*4 + 0)*64 + cl] + buf[(wnn*4 + 1)*64 + cl]
                    + buf[(wnn*4 + 2)*64 + cl] + buf[(wnn*4 + 3)*64 + cl];
            atomicAdd(&g_csum[(bm >> 12)*1024 + bn + tid], s);
        }
    }
}

// ---------------- stage5: attp[l][d] += v[t][l]*expk[t][d], ldsm.trans -----
// 4 t-splits of 1024; tiles in natural [t][feat] layout, ldmatrix.trans
__global__ void __launch_bounds__(256) stage5_partial() {
    extern __shared__ char sm5[];
    char* Vt = sm5;            // [128 t][128 l] fp16, 32KB
    char* Kt = sm5 + 32768;    // [128 t][128 d] fp16, 32KB
    uint32_t vbase = (uint32_t)__cvta_generic_to_shared(Vt);
    uint32_t kbase = (uint32_t)__cvta_generic_to_shared(Kt);

    int bh = blockIdx.x;               // 0..31
    int b = bh >> 3, h = bh & 7;
    int sp = blockIdx.y;               // 0..3 (1024 t each)

    int tid = threadIdx.x;
    int lane = tid & 31, wid = tid >> 5;
    int wm = wid & 3, wn = wid >> 2;
    int q = lane >> 3, r = lane & 7;
    int grp = lane >> 2, tg = lane & 3;

    float acc[2][8][4];
#pragma unroll
    for (int i = 0; i < 2; i++)
#pragma unroll
        for (int j = 0; j < 8; j++)
#pragma unroll
            for (int e = 0; e < 4; e++) acc[i][j][e] = 0.f;

    for (int c = 0; c < 8; c++) {
        int t0 = sp*1024 + c*128;
        __syncthreads();
#pragma unroll
        for (int i = 0; i < 8; i++) {
            int idx = tid + i*256;
            int trow = idx >> 4, cg = idx & 15;
            size_t src = ((size_t)(b*T_ + t0 + trow))*D_ + h*128 + cg*8;
            unsigned ph = trow*256 + (((cg ^ (trow & 7)) << 4));
            cp_async16(Kt + ph, g_k + src);
            cp_async16(Vt + ph, g_v + src);
        }
        CP_COMMIT();
        CP_WAIT(0);
        __syncthreads();

#pragma unroll
        for (int ks = 0; ks < 8; ks++) {
            uint32_t a[2][4], bfr[4][4];
#pragma unroll
            for (int mi = 0; mi < 2; mi++) {
                int trow = ks*16 + ((q >> 1) << 3) + r;
                int mcg  = wm*4 + mi*2 + (q & 1);
                ldsm4t(a[mi], vbase + trow*256 + (((mcg ^ (trow & 7)) << 4)));
            }
#pragma unroll
            for (int nj = 0; nj < 4; nj++) {
                int trow = ks*16 + ((q & 1) << 3) + r;
                int dcg  = wn*8 + nj*2 + (q >> 1);
                ldsm4t(bfr[nj], kbase + trow*256 + (((dcg ^ (trow & 7)) << 4)));
            }
#pragma unroll
            for (int mi = 0; mi < 2; mi++)
#pragma unroll
                for (int nj = 0; nj < 4; nj++) {
                    mma16(acc[mi][nj*2 + 0], a[mi], &bfr[nj][0]);
                    mma16(acc[mi][nj*2 + 1], a[mi], &bfr[nj][2]);
                }
        }
    }

    float* outp = g_attp + ((size_t)(sp*32 + bh))*16384;   // [l][d]
#pragma unroll
    for (int mi = 0; mi < 2; mi++)
#pragma unroll
        for (int ni = 0; ni < 8; ni++) {
            int row = wm*32 + mi*16 + grp;
            int cc  = wn*64 + ni*8 + tg*2;
            *(float2*)(outp + row*128 + cc) =
                make_float2(acc[mi][ni][0], acc[mi][ni][1]);
            *(float2*)(outp + (row+8)*128 + cc) =
                make_float2(acc[mi][ni][2], acc[mi][ni][3]);
        }
}

// ---------------- reduce splits + divide by csum (fp16 out) ----------------
__global__ void stage5_reduce() {
    int idx = blockIdx.x*256 + threadIdx.x;
    int bh = idx >> 14;
    int rem = idx & 16383;                      // l*128 + d
    int dd = rem & 127;
    int b = bh >> 3, h = bh & 7;
    float s = 0.f;
#pragma unroll
    for (int sp = 0; sp < 4; sp++) s += g_attp[((size_t)(sp*32 + bh))*16384 + rem];
    g_att[(size_t)bh*16384 + rem] = __float2half_rn(s / g_csum[b*D_ + h*128 + dd]);
}

// ---------------- stage6: y = softmax_hd(q) @ att, fp16 mma ----------------
__global__ void __launch_bounds__(256) stage6(float* __restrict__ out) {
    extern __shared__ char sm6[];
    char* qs   = sm6;
    char* attB = sm6 + 32768;
    uint32_t qbase = (uint32_t)__cvta_generic_to_shared(qs);
    uint32_t abase = (uint32_t)__cvta_generic_to_shared(attB);

    int rb = blockIdx.x;
    int h  = blockIdx.y;
    int r0 = rb * 128;
    int b  = r0 >> 12;
    const __half* attm = g_att + ((size_t)(b*8 + h))*16384;

    int tid = threadIdx.x;
    int lane = tid & 31, wid = tid >> 5;
    int wm = wid & 3, wn = wid >> 2;
    int q = lane >> 3, r = lane & 7;
    int grp = lane >> 2, tg = lane & 3;

#pragma unroll
    for (int i = 0; i < 8; i++) {
        int idx = tid + i*256;
        int c = idx >> 10;
        int rem = idx & 1023;
        int row = rem >> 3;
        int g = rem & 7;
        cp_async16(attB + c*16384 + row*128 + ((g ^ (row & 7)) << 4),
                   attm + row*128 + c*64 + g*8);
    }
    CP_COMMIT();

    int rown = tid >> 3;
    int lane8 = tid & 7;
#pragma unroll
    for (int rr = 0; rr < 4; rr++) {
        int arl = rr*32 + rown;
        const __half* qrow = g_q + (size_t)(r0 + arl)*D_ + h*128 + lane8*16;
        uint4 p0 = *(const uint4*)qrow;
        uint4 p1 = *(const uint4*)(qrow + 8);
        float e[16];
        const __half2* hp0 = (const __half2*)&p0;
        const __half2* hp1 = (const __half2*)&p1;
#pragma unroll
        for (int j = 0; j < 4; j++) {
            float2 f0 = __half22float2(hp0[j]);
            float2 f1 = __half22float2(hp1[j]);
            e[j*2]   = f0.x; e[j*2+1]   = f0.y;
            e[8+j*2] = f1.x; e[8+j*2+1] = f1.y;
        }
        float mx = e[0];
#pragma unroll
        for (int j = 1; j < 16; j++) mx = fmaxf(mx, e[j]);
#pragma unroll
        for (int o = 4; o; o >>= 1) mx = fmaxf(mx, __shfl_xor_sync(0xffffffffu, mx, o));
        float sm = 0.f;
#pragma unroll
        for (int j = 0; j < 16; j++) { e[j] = __expf(e[j] - mx); sm += e[j]; }
#pragma unroll
        for (int o = 4; o; o >>= 1) sm += __shfl_xor_sync(0xffffffffu, sm, o);
        float inv = 1.f / sm;
        uint4 o0, o1;
        __half2* op0 = (__half2*)&o0;
        __half2* op1 = (__half2*)&o1;
#pragma unroll
        for (int j = 0; j < 4; j++) {
            op0[j] = __floats2half2_rn(e[j*2]*inv,   e[j*2+1]*inv);
            op1[j] = __floats2half2_rn(e[8+j*2]*inv, e[8+j*2+1]*inv);
        }
        int ch = lane8 >> 2;
        int cg = (lane8 & 3)*2;
        char* dst = qs + ch*16384 + arl*128;
        *(uint4*)(dst + (((cg    ) ^ (arl & 7)) << 4)) = o0;
        *(uint4*)(dst + (((cg + 1) ^ (arl & 7)) << 4)) = o1;
    }
    CP_WAIT(0);
    __syncthreads();

    float acc[2][8][4];
#pragma unroll
    for (int i = 0; i < 2; i++)
#pragma unroll
        for (int j = 0; j < 8; j++)
#pragma unroll
            for (int e = 0; e < 4; e++) acc[i][j][e] = 0.f;

#pragma unroll
    for (int c = 0; c < 2; c++) {
        uint32_t Asm = qbase + c*16384;
        uint32_t Bsm = abase + c*16384;
#pragma unroll
        for (int ks = 0; ks < 4; ks++) {
            uint32_t a[2][4], bfr[4][4];
#pragma unroll
            for (int mi = 0; mi < 2; mi++) {
                int row = wm*32 + mi*16 + r + ((q & 1) << 3);
                int kh  = ks*16 + ((q >> 1) << 3);
                ldsm4(a[mi], Asm + row*128 + (((kh >> 3) ^ (row & 7)) << 4));
            }
#pragma unroll
            for (int nj = 0; nj < 4; nj++) {
                int nrow = wn*64 + nj*16 + r + ((q >> 1) << 3);
                int kh   = ks*16 + ((q & 1) << 3);
                ldsm4(bfr[nj], Bsm + nrow*128 + (((kh >> 3) ^ (nrow & 7)) << 4));
            }
#pragma unroll
            for (int mi = 0; mi < 2; mi++)
#pragma unroll
                for (int nj = 0; nj < 4; nj++) {
                    mma16(acc[mi][nj*2 + 0], a[mi], &bfr[nj][0]);
                    mma16(acc[mi][nj*2 + 1], a[mi], &bfr[nj][2]);
                }
        }
    }

#pragma unroll
    for (int mi = 0; mi < 2; mi++)
#pragma unroll
        for (int ni = 0; ni < 8; ni++) {
            int row = r0 + wm*32 + mi*16 + grp;
            int cc  = h*128 + wn*64 + ni*8 + tg*2;
            *(float2*)(out + (size_t)row*D_ + cc) =
                make_float2(acc[mi][ni][0], acc[mi][ni][1]);
            *(float2*)(out + (size_t)(row+8)*D_ + cc) =
                make_float2(acc[mi][ni][2], acc[mi][ni][3]);
        }
}

// ---------------------------------------------------------------------------
extern "C" void kernel_launch(void* const* d_in, const int* in_sizes, int n_in,
                              void* d_out, int out_size) {
    const float* x  = (const float*)d_in[0];
    const float* nw = (const float*)d_in[1];
    const float* nb = (const float*)d_in[2];
    const float* tw = (const float*)d_in[3];
    const float* tb = (const float*)d_in[4];
    const float* Wq = (const float*)d_in[5];
    const float* bq = (const float*)d_in[6];
    const float* Wk = (const float*)d_in[7];
    const float* bk = (const float*)d_in[8];
    const float* Wv = (const float*)d_in[9];
    const float* bv = (const float*)d_in[10];
    float* out = (float*)d_out;

    cudaFuncSetAttribute(gemm_f16,       cudaFuncAttributeMaxDynamicSharedMemorySize, 98304);
    cudaFuncSetAttribute(stage5_partial, cudaFuncAttributeMaxDynamicSharedMemorySize, 65536);
    cudaFuncSetAttribute(stage6,         cudaFuncAttributeMaxDynamicSharedMemorySize, 65536);

    cvt_w1<<<1024, 256>>>(Wq, 0);                          // 0 (also zeroes csum)
    cvt_w1<<<1024, 256>>>(Wk, 1);                          // 1
    cvt_w1<<<1024, 256>>>(Wv, 2);                          // 2
    ln_kernel<<<R_, 256>>>(x, nw, nb, tw, tb);             // 3

    gemm_f16<<<dim3(8, 128, 3), 256, 98304>>>(bq, bk, bv); // 4

    stage5_partial<<<dim3(32, 4), 256, 65536>>>();         // 5 <- ncu capture
    stage5_reduce<<<(32*16384)/256, 256>>>();              // 6
    stage6<<<dim3(128, 8), 256, 65536>>>(out);             // 7
}

// round 13
// speedup vs baseline: 1.0240x; 1.0240x over previous
#include <cuda_runtime.h>
#include <cuda_fp16.h>
#include <cstdint>

#define T_  4096
#define B_  4
#define D_  1024
#define H_  8
#define R_  (T_*B_)   // 16384 rows

// ---------------- scratch -------------------------------------------------
__device__ __align__(16) __half g_xn [(size_t)R_*D_];
__device__ __align__(16) __half g_xtn[(size_t)R_*D_];
__device__ __align__(16) __half g_q  [(size_t)R_*D_];
__device__ __align__(16) __half g_k  [(size_t)R_*D_];   // holds exp(k + bias)
__device__ __align__(16) __half g_v  [(size_t)R_*D_];
__device__ __align__(16) __half g_wh[3u*1024*1024];
__device__ __align__(16) float g_csum[B_*D_];
__device__ __align__(16) float g_attp[8ull*32*16384];    // [split][bh][l][d] fp32
__device__ __align__(16) __half g_att [(size_t)32*16384]; // [bh][l][d] fp16

// ---------------- helpers -------------------------------------------------
__device__ __forceinline__ void cp_async16(void* smem, const void* gmem) {
    unsigned sa = (unsigned)__cvta_generic_to_shared(smem);
    asm volatile("cp.async.cg.shared.global [%0], [%1], 16;\n" :: "r"(sa), "l"(gmem));
}
#define CP_COMMIT()  asm volatile("cp.async.commit_group;\n")
#define CP_WAIT(n)   asm volatile("cp.async.wait_group %0;\n" :: "n"(n))

__device__ __forceinline__ void mma16(float* d, const uint32_t* a, const uint32_t* b) {
    asm volatile(
        "mma.sync.aligned.m16n8k16.row.col.f32.f16.f16.f32 "
        "{%0,%1,%2,%3}, {%4,%5,%6,%7}, {%8,%9}, {%0,%1,%2,%3};"
        : "+f"(d[0]), "+f"(d[1]), "+f"(d[2]), "+f"(d[3])
        : "r"(a[0]), "r"(a[1]), "r"(a[2]), "r"(a[3]), "r"(b[0]), "r"(b[1]));
}
__device__ __forceinline__ void ldsm4(uint32_t* r, uint32_t addr) {
    asm volatile("ldmatrix.sync.aligned.m8n8.x4.shared.b16 {%0,%1,%2,%3}, [%4];"
        : "=r"(r[0]), "=r"(r[1]), "=r"(r[2]), "=r"(r[3]) : "r"(addr));
}
__device__ __forceinline__ void ldsm4t(uint32_t* r, uint32_t addr) {
    asm volatile("ldmatrix.sync.aligned.m8n8.x4.trans.shared.b16 {%0,%1,%2,%3}, [%4];"
        : "=r"(r[0]), "=r"(r[1]), "=r"(r[2]), "=r"(r[3]) : "r"(addr));
}

// ---------------- weight convert to fp16 (all 3) + csum zeroing ------------
__global__ void cvt_w(const float* __restrict__ w0, const float* __restrict__ w1,
                      const float* __restrict__ w2) {
    int i4 = blockIdx.x*256 + threadIdx.x;        // 3*262144 float4s
    if (blockIdx.x < 16)
        g_csum[blockIdx.x*256 + threadIdx.x] = 0.f;
    int which = i4 >> 18;
    int off = i4 & 262143;
    const float* s = (which == 0) ? w0 : (which == 1 ? w1 : w2);
    float4 v = *(const float4*)(s + (size_t)off*4);
    __half2 h0 = __floats2half2_rn(v.x, v.y);
    __half2 h1 = __floats2half2_rn(v.z, v.w);
    *(uint2*)(g_wh + (size_t)which*1048576 + (size_t)off*4) =
        make_uint2(*(unsigned*)&h0, *(unsigned*)&h1);
}

// ---------------- LayerNorm (both branches, fp16 out, float4 loads) --------
__global__ void ln_kernel(const float* __restrict__ x,
                          const float* __restrict__ nw, const float* __restrict__ nb,
                          const float* __restrict__ tw, const float* __restrict__ tb) {
    int rin = blockIdx.x;
    int t = rin / B_, b = rin % B_;
    const float* xr = x + (size_t)rin * D_;
    int tid = threadIdx.x;

    float4 v = *(const float4*)(xr + tid*4);
    float s  = v.x + v.y + v.z + v.w;
    float s2 = v.x*v.x + v.y*v.y + v.z*v.z + v.w*v.w;

    __shared__ float red[40];
#pragma unroll
    for (int o = 16; o; o >>= 1) {
        s  += __shfl_xor_sync(0xffffffffu, s,  o);
        s2 += __shfl_xor_sync(0xffffffffu, s2, o);
    }
    if ((tid & 31) == 0) { red[tid>>5] = s; red[8 + (tid>>5)] = s2; }
    __syncthreads();
    if (tid < 32) {
        float a = (tid < 8) ? red[tid]     : 0.f;
        float c = (tid < 8) ? red[8 + tid] : 0.f;
#pragma unroll
        for (int o = 4; o; o >>= 1) {
            a += __shfl_xor_sync(0xffffffffu, a, o);
            c += __shfl_xor_sync(0xffffffffu, c, o);
        }
        if (tid == 0) { red[32] = a; red[33] = c; }
    }
    __syncthreads();
    float mean = red[32] * (1.f / D_);
    float var  = red[33] * (1.f / D_) - mean*mean;
    float rstd = rsqrtf(var + 1e-5f);

    float4 w1 = *(const float4*)(nw + tid*4);
    float4 b1 = *(const float4*)(nb + tid*4);
    float4 w2 = *(const float4*)(tw + tid*4);
    float4 b2 = *(const float4*)(tb + tid*4);

    float z0 = (v.x - mean)*rstd, z1 = (v.y - mean)*rstd;
    float z2 = (v.z - mean)*rstd, z3 = (v.w - mean)*rstd;

    size_t ro = ((size_t)b*T_ + t) * D_ + tid*4;
    __half2 n0 = __floats2half2_rn(z0*w1.x + b1.x, z1*w1.y + b1.y);
    __half2 n1 = __floats2half2_rn(z2*w1.z + b1.z, z3*w1.w + b1.w);
    *(uint2*)(g_xn + ro) = make_uint2(*(unsigned*)&n0, *(unsigned*)&n1);
    __half2 t0 = __floats2half2_rn(z0*w2.x + b2.x, z1*w2.y + b2.y);
    __half2 t1 = __floats2half2_rn(z2*w2.z + b2.z, z3*w2.w + b2.w);
    *(uint2*)(g_xtn + ro) = make_uint2(*(unsigned*)&t0, *(unsigned*)&t1);
}

// ---------------- fp16 GEMM: 128x128 block, 8 warps, 32x64 warp tile -------
// mode 1 (k): stores exp(acc + bias) AND accumulates column sums into g_csum.
__global__ void __launch_bounds__(256, 2)
gemm_f16(const float* __restrict__ bq, const float* __restrict__ bk,
         const float* __restrict__ bv) {
    extern __shared__ char smraw[];
    uint32_t sbase = (uint32_t)__cvta_generic_to_shared(smraw);
    int mode = blockIdx.z;
    const __half* A = (mode == 0) ? g_xn : g_xtn;
    const __half* W = g_wh + (size_t)mode*1048576;
    __half*       C = (mode == 0) ? g_q : (mode == 1 ? g_k : g_v);
    const float*  bias = (mode == 0) ? bq : (mode == 1 ? bk : bv);

    int tid = threadIdx.x;
    int lane = tid & 31, wid = tid >> 5;
    int wm = wid & 3, wn = wid >> 2;      // 4x2 warps, warp tile 32x64
    int bm = blockIdx.y * 128, bn = blockIdx.x * 128;

    int q = lane >> 3, r = lane & 7;
    int grp = lane >> 2, tg = lane & 3;

    float acc[2][8][4];
#pragma unroll
    for (int i = 0; i < 2; i++)
#pragma unroll
        for (int j = 0; j < 8; j++)
#pragma unroll
            for (int e = 0; e < 4; e++) acc[i][j][e] = 0.f;

#define LOAD_CHUNK(S, KC)                                                        \
    {                                                                            \
        char* As_ = smraw + (S)*32768;                                           \
        char* Bs_ = As_ + 16384;                                                 \
        _Pragma("unroll")                                                        \
        for (int i = 0; i < 4; i++) {                                            \
            int idx = tid + i*256;                                               \
            int rr = idx >> 3, g = idx & 7;                                      \
            cp_async16(As_ + rr*128 + ((g ^ (rr & 7)) << 4),                     \
                       A + (size_t)(bm + rr)*1024 + (KC)*64 + g*8);              \
            cp_async16(Bs_ + rr*128 + ((g ^ (rr & 7)) << 4),                     \
                       W + (size_t)(bn + rr)*1024 + (KC)*64 + g*8);              \
        }                                                                        \
        CP_COMMIT();                                                             \
    }

    LOAD_CHUNK(0, 0)
    LOAD_CHUNK(1, 1)

    for (int c = 0; c < 16; c++) {
        if (c < 15) { CP_WAIT(1); } else { CP_WAIT(0); }
        __syncthreads();
        if (c + 2 < 16) { LOAD_CHUNK((c + 2) % 3, c + 2) }

        uint32_t Asm = sbase + (c % 3)*32768;
        uint32_t Bsm = Asm + 16384;
#pragma unroll
        for (int ks = 0; ks < 4; ks++) {
            uint32_t a[2][4], bfr[4][4];
#pragma unroll
            for (int mi = 0; mi < 2; mi++) {
                int row = wm*32 + mi*16 + r + ((q & 1) << 3);
                int kh  = ks*16 + ((q >> 1) << 3);
                ldsm4(a[mi], Asm + row*128 + (((kh >> 3) ^ (row & 7)) << 4));
            }
#pragma unroll
            for (int nj = 0; nj < 4; nj++) {
                int nrow = wn*64 + nj*16 + r + ((q >> 1) << 3);
                int kh   = ks*16 + ((q & 1) << 3);
                ldsm4(bfr[nj], Bsm + nrow*128 + (((kh >> 3) ^ (nrow & 7)) << 4));
            }
#pragma unroll
            for (int mi = 0; mi < 2; mi++)
#pragma unroll
                for (int nj = 0; nj < 4; nj++) {
                    mma16(acc[mi][nj*2 + 0], a[mi], &bfr[nj][0]);
                    mma16(acc[mi][nj*2 + 1], a[mi], &bfr[nj][2]);
                }
        }
    }
#undef LOAD_CHUNK

    float cs0[8], cs1[8];
#pragma unroll
    for (int ni = 0; ni < 8; ni++) { cs0[ni] = 0.f; cs1[ni] = 0.f; }

#pragma unroll
    for (int mi = 0; mi < 2; mi++)
#pragma unroll
        for (int ni = 0; ni < 8; ni++) {
            int row = bm + wm*32 + mi*16 + grp;
            int col = bn + wn*64 + ni*8 + tg*2;
            float b0 = bias[col], b1 = bias[col + 1];
            float v0 = acc[mi][ni][0] + b0, v1 = acc[mi][ni][1] + b1;
            float v2 = acc[mi][ni][2] + b0, v3 = acc[mi][ni][3] + b1;
            if (mode == 1) {
                v0 = __expf(v0); v1 = __expf(v1);
                v2 = __expf(v2); v3 = __expf(v3);
                cs0[ni] += v0 + v2;
                cs1[ni] += v1 + v3;
            }
            *(__half2*)(C + (size_t)row*1024 + col) = __floats2half2_rn(v0, v1);
            *(__half2*)(C + (size_t)(row + 8)*1024 + col) = __floats2half2_rn(v2, v3);
        }

    if (mode == 1) {
#pragma unroll
        for (int ni = 0; ni < 8; ni++) {
#pragma unroll
            for (int o = 4; o <= 16; o <<= 1) {
                cs0[ni] += __shfl_xor_sync(0xffffffffu, cs0[ni], o);
                cs1[ni] += __shfl_xor_sync(0xffffffffu, cs1[ni], o);
            }
        }
        __syncthreads();
        float* buf = (float*)smraw;      // [8 warps][64 cols]
        if (lane < 4) {
#pragma unroll
            for (int ni = 0; ni < 8; ni++) {
                buf[wid*64 + ni*8 + tg*2    ] = cs0[ni];
                buf[wid*64 + ni*8 + tg*2 + 1] = cs1[ni];
            }
        }
        __syncthreads();
        if (tid < 128) {
            int wnn = tid >> 6, cl = tid & 63;
            float s = buf[(wnn*4 + 0)*64 + cl] + buf[(wnn*4 + 1)*64 + cl]
                    + buf[(wnn*4 + 2)*64 + cl] + buf[(wnn*4 + 3)*64 + cl];
            atomicAdd(&g_csum[(bm >> 12)*1024 + bn + tid], s);
        }
    }
}

// ---------------- stage5: attp[l][d] += v[t][l]*expk[t][d], ldsm.trans -----
// 8 t-splits of 512; tiles in natural [t][feat] layout, ldmatrix.trans
__global__ void __launch_bounds__(256) stage5_partial() {
    extern __shared__ char sm5[];
    char* Vt = sm5;            // [128 t][128 l] fp16, 32KB
    char* Kt = sm5 + 32768;    // [128 t][128 d] fp16, 32KB
    uint32_t vbase = (uint32_t)__cvta_generic_to_shared(Vt);
    uint32_t kbase = (uint32_t)__cvta_generic_to_shared(Kt);

    int bh = blockIdx.x;               // 0..31
    int b = bh >> 3, h = bh & 7;
    int sp = blockIdx.y;               // 0..7 (512 t each)

    int tid = threadIdx.x;
    int lane = tid & 31, wid = tid >> 5;
    int wm = wid & 3, wn = wid >> 2;
    int q = lane >> 3, r = lane & 7;
    int grp = lane >> 2, tg = lane & 3;

    float acc[2][8][4];
#pragma unroll
    for (int i = 0; i < 2; i++)
#pragma unroll
        for (int j = 0; j < 8; j++)
#pragma unroll
            for (int e = 0; e < 4; e++) acc[i][j][e] = 0.f;

    for (int c = 0; c < 4; c++) {
        int t0 = sp*512 + c*128;
        __syncthreads();
#pragma unroll
        for (int i = 0; i < 8; i++) {
            int idx = tid + i*256;
            int trow = idx >> 4, cg = idx & 15;
            size_t src = ((size_t)(b*T_ + t0 + trow))*D_ + h*128 + cg*8;
            unsigned ph = trow*256 + (((cg ^ (trow & 7)) << 4));
            cp_async16(Kt + ph, g_k + src);
            cp_async16(Vt + ph, g_v + src);
        }
        CP_COMMIT();
        CP_WAIT(0);
        __syncthreads();

#pragma unroll
        for (int ks = 0; ks < 8; ks++) {
            uint32_t a[2][4], bfr[4][4];
#pragma unroll
            for (int mi = 0; mi < 2; mi++) {
                int trow = ks*16 + ((q >> 1) << 3) + r;
                int mcg  = wm*4 + mi*2 + (q & 1);
                ldsm4t(a[mi], vbase + trow*256 + (((mcg ^ (trow & 7)) << 4)));
            }
#pragma unroll
            for (int nj = 0; nj < 4; nj++) {
                int trow = ks*16 + ((q & 1) << 3) + r;
                int dcg  = wn*8 + nj*2 + (q >> 1);
                ldsm4t(bfr[nj], kbase + trow*256 + (((dcg ^ (trow & 7)) << 4)));
            }
#pragma unroll
            for (int mi = 0; mi < 2; mi++)
#pragma unroll
                for (int nj = 0; nj < 4; nj++) {
                    mma16(acc[mi][nj*2 + 0], a[mi], &bfr[nj][0]);
                    mma16(acc[mi][nj*2 + 1], a[mi], &bfr[nj][2]);
                }
        }
    }

    float* outp = g_attp + ((size_t)(sp*32 + bh))*16384;   // [l][d]
#pragma unroll
    for (int mi = 0; mi < 2; mi++)
#pragma unroll
        for (int ni = 0; ni < 8; ni++) {
            int row = wm*32 + mi*16 + grp;
            int cc  = wn*64 + ni*8 + tg*2;
            *(float2*)(outp + row*128 + cc) =
                make_float2(acc[mi][ni][0], acc[mi][ni][1]);
            *(float2*)(outp + (row+8)*128 + cc) =
                make_float2(acc[mi][ni][2], acc[mi][ni][3]);
        }
}

// ---------------- reduce splits + divide by csum (fp16 out) ----------------
__global__ void stage5_reduce() {
    int idx = blockIdx.x*256 + threadIdx.x;
    int bh = idx >> 14;
    int rem = idx & 16383;                      // l*128 + d
    int dd = rem & 127;
    int b = bh >> 3, h = bh & 7;
    float s = 0.f;
#pragma unroll
    for (int sp = 0; sp < 8; sp++) s += g_attp[((size_t)(sp*32 + bh))*16384 + rem];
    g_att[(size_t)bh*16384 + rem] = __float2half_rn(s / g_csum[b*D_ + h*128 + dd]);
}

// ---------------- stage6: y = softmax_hd(q) @ att, fp16 mma ----------------
__global__ void __launch_bounds__(256) stage6(float* __restrict__ out) {
    extern __shared__ char sm6[];
    char* qs   = sm6;
    char* attB = sm6 + 32768;
    uint32_t qbase = (uint32_t)__cvta_generic_to_shared(qs);
    uint32_t abase = (uint32_t)__cvta_generic_to_shared(attB);

    int rb = blockIdx.x;
    int h  = blockIdx.y;
    int r0 = rb * 128;
    int b  = r0 >> 12;
    const __half* attm = g_att + ((size_t)(b*8 + h))*16384;

    int tid = threadIdx.x;
    int lane = tid & 31, wid = tid >> 5;
    int wm = wid & 3, wn = wid >> 2;
    int q = lane >> 3, r = lane & 7;
    int grp = lane >> 2, tg = lane & 3;

#pragma unroll
    for (int i = 0; i < 8; i++) {
        int idx = tid + i*256;
        int c = idx >> 10;
        int rem = idx & 1023;
        int row = rem >> 3;
        int g = rem & 7;
        cp_async16(attB + c*16384 + row*128 + ((g ^ (row & 7)) << 4),
                   attm + row*128 + c*64 + g*8);
    }
    CP_COMMIT();

    int rown = tid >> 3;
    int lane8 = tid & 7;
#pragma unroll
    for (int rr = 0; rr < 4; rr++) {
        int arl = rr*32 + rown;
        const __half* qrow = g_q + (size_t)(r0 + arl)*D_ + h*128 + lane8*16;
        uint4 p0 = *(const uint4*)qrow;
        uint4 p1 = *(const uint4*)(qrow + 8);
        float e[16];
        const __half2* hp0 = (const __half2*)&p0;
        const __half2* hp1 = (const __half2*)&p1;
#pragma unroll
        for (int j = 0; j < 4; j++) {
            float2 f0 = __half22float2(hp0[j]);
            float2 f1 = __half22float2(hp1[j]);
            e[j*2]   = f0.x; e[j*2+1]   = f0.y;
            e[8+j*2] = f1.x; e[8+j*2+1] = f1.y;
        }
        float mx = e[0];
#pragma unroll
        for (int j = 1; j < 16; j++) mx = fmaxf(mx, e[j]);
#pragma unroll
        for (int o = 4; o; o >>= 1) mx = fmaxf(mx, __shfl_xor_sync(0xffffffffu, mx, o));
        float sm = 0.f;
#pragma unroll
        for (int j = 0; j < 16; j++) { e[j] = __expf(e[j] - mx); sm += e[j]; }
#pragma unroll
        for (int o = 4; o; o >>= 1) sm += __shfl_xor_sync(0xffffffffu, sm, o);
        float inv = 1.f / sm;
        uint4 o0, o1;
        __half2* op0 = (__half2*)&o0;
        __half2* op1 = (__half2*)&o1;
#pragma unroll
        for (int j = 0; j < 4; j++) {
            op0[j] = __floats2half2_rn(e[j*2]*inv,   e[j*2+1]*inv);
            op1[j] = __floats2half2_rn(e[8+j*2]*inv, e[8+j*2+1]*inv);
        }
        int ch = lane8 >> 2;
        int cg = (lane8 & 3)*2;
        char* dst = qs + ch*16384 + arl*128;
        *(uint4*)(dst + (((cg    ) ^ (arl & 7)) << 4)) = o0;
        *(uint4*)(dst + (((cg + 1) ^ (arl & 7)) << 4)) = o1;
    }
    CP_WAIT(0);
    __syncthreads();

    float acc[2][8][4];
#pragma unroll
    for (int i = 0; i < 2; i++)
#pragma unroll
        for (int j = 0; j < 8; j++)
#pragma unroll
            for (int e = 0; e < 4; e++) acc[i][j][e] = 0.f;

#pragma unroll
    for (int c = 0; c < 2; c++) {
        uint32_t Asm = qbase + c*16384;
        uint32_t Bsm = abase + c*16384;
#pragma unroll
        for (int ks = 0; ks < 4; ks++) {
            uint32_t a[2][4], bfr[4][4];
#pragma unroll
            for (int mi = 0; mi < 2; mi++) {
                int row = wm*32 + mi*16 + r + ((q & 1) << 3);
                int kh  = ks*16 + ((q >> 1) << 3);
                ldsm4(a[mi], Asm + row*128 + (((kh >> 3) ^ (row & 7)) << 4));
            }
#pragma unroll
            for (int nj = 0; nj < 4; nj++) {
                int nrow = wn*64 + nj*16 + r + ((q >> 1) << 3);
                int kh   = ks*16 + ((q & 1) << 3);
                ldsm4(bfr[nj], Bsm + nrow*128 + (((kh >> 3) ^ (nrow & 7)) << 4));
            }
#pragma unroll
            for (int mi = 0; mi < 2; mi++)
#pragma unroll
                for (int nj = 0; nj < 4; nj++) {
                    mma16(acc[mi][nj*2 + 0], a[mi], &bfr[nj][0]);
                    mma16(acc[mi][nj*2 + 1], a[mi], &bfr[nj][2]);
                }
        }
    }

#pragma unroll
    for (int mi = 0; mi < 2; mi++)
#pragma unroll
        for (int ni = 0; ni < 8; ni++) {
            int row = r0 + wm*32 + mi*16 + grp;
            int cc  = h*128 + wn*64 + ni*8 + tg*2;
            *(float2*)(out + (size_t)row*D_ + cc) =
                make_float2(acc[mi][ni][0], acc[mi][ni][1]);
            *(float2*)(out + (size_t)(row+8)*D_ + cc) =
                make_float2(acc[mi][ni][2], acc[mi][ni][3]);
        }
}

// ---------------------------------------------------------------------------
extern "C" void kernel_launch(void* const* d_in, const int* in_sizes, int n_in,
                              void* d_out, int out_size) {
    const float* x  = (const float*)d_in[0];
    const float* nw = (const float*)d_in[1];
    const float* nb = (const float*)d_in[2];
    const float* tw = (const float*)d_in[3];
    const float* tb = (const float*)d_in[4];
    const float* Wq = (const float*)d_in[5];
    const float* bq = (const float*)d_in[6];
    const float* Wk = (const float*)d_in[7];
    const float* bk = (const float*)d_in[8];
    const float* Wv = (const float*)d_in[9];
    const float* bv = (const float*)d_in[10];
    float* out = (float*)d_out;

    cudaFuncSetAttribute(gemm_f16,       cudaFuncAttributeMaxDynamicSharedMemorySize, 98304);
    cudaFuncSetAttribute(stage5_partial, cudaFuncAttributeMaxDynamicSharedMemorySize, 65536);
    cudaFuncSetAttribute(stage6,         cudaFuncAttributeMaxDynamicSharedMemorySize, 65536);

    cvt_w<<<3072, 256>>>(Wq, Wk, Wv);                      // 0 (also zeroes csum)
    ln_kernel<<<R_, 256>>>(x, nw, nb, tw, tb);             // 1

    gemm_f16<<<dim3(8, 128, 3), 256, 98304>>>(bq, bk, bv); // 2

    stage5_partial<<<dim3(32, 8), 256, 65536>>>();         // 3
    stage5_reduce<<<(32*16384)/256, 256>>>();              // 4
    stage6<<<dim3(128, 8), 256, 65536>>>(out);             // 5
}